// round 13
// baseline (speedup 1.0000x reference)
#include <cuda_runtime.h>
#include <math.h>

// ---------------------------------------------------------------------------
// Problem constants (Swin block: B=16, 56x56, C=384, 12 heads, ws=7, shift=3)
// ---------------------------------------------------------------------------
#define CC     384
#define NHEADS 12
#define HD     32
#define NTOK   49          // 7*7 tokens per window
#define NWIN   1024        // 16 * 8 * 8 windows
#define TOT    50176       // 16 * 56 * 56 tokens
#define HIDDEN 1536
#define C3     1152        // 3*C

// ---------------------------------------------------------------------------
// Scratch buffers (allocation-free: __device__ globals)
// ---------------------------------------------------------------------------
__device__ float g_xw  [TOT * CC];       // LN1(windowed) input / reused for LN2 out
__device__ float g_qkv [TOT * C3];       // qkv activations
__device__ float g_attn[TOT * CC];       // attention output (window-major)
__device__ float g_xnew[TOT * CC];       // x after attention residual
__device__ float g_hid [TOT * HIDDEN];   // mlp hidden

// ---------------------------------------------------------------------------
// window-major row index -> original token index (also used for the inverse
// scatter: roll(-3) gather and roll(+3) scatter are the same (c+3)%56 map)
// ---------------------------------------------------------------------------
__device__ __forceinline__ int win_to_token(int r) {
    int w  = r / 49;
    int p  = r - w * 49;
    int b  = w >> 6;
    int wy = (w >> 3) & 7;
    int wx = w & 7;
    int iy = p / 7;
    int ix = p - iy * 7;
    int hs = wy * 7 + iy + 3; if (hs >= 56) hs -= 56;
    int ws = wx * 7 + ix + 3; if (ws >= 56) ws -= 56;
    return b * 3136 + hs * 56 + ws;
}

__device__ __forceinline__ float gelu_exact(float v) {
    return 0.5f * v * (1.0f + erff(v * 0.70710678118654752440f));
}

// ---------------------------------------------------------------------------
// LayerNorm, warp per token. GATHER=true: destination is window-major, source
// gathered through the shift+partition map (LN1). GATHER=false: identity (LN2).
// ---------------------------------------------------------------------------
template<bool GATHER>
__global__ __launch_bounds__(256)
void ln_kernel(const float* __restrict__ x, const float* __restrict__ gw,
               const float* __restrict__ gb, float* __restrict__ out)
{
    int warp = threadIdx.x >> 5;
    int lane = threadIdx.x & 31;
    int t = blockIdx.x * 8 + warp;                 // TOT divisible by 8
    int src = GATHER ? win_to_token(t) : t;
    const float* xr = x + (size_t)src * CC;

    float v[12];
    float s = 0.f;
    #pragma unroll
    for (int i = 0; i < 12; i++) { v[i] = xr[lane + 32 * i]; s += v[i]; }
    #pragma unroll
    for (int o = 16; o; o >>= 1) s += __shfl_xor_sync(0xffffffffu, s, o);
    float mu = s * (1.0f / 384.0f);

    float var = 0.f;
    #pragma unroll
    for (int i = 0; i < 12; i++) { float d = v[i] - mu; var += d * d; }
    #pragma unroll
    for (int o = 16; o; o >>= 1) var += __shfl_xor_sync(0xffffffffu, var, o);
    float rstd = rsqrtf(var * (1.0f / 384.0f) + 1e-5f);

    float* orow = out + (size_t)t * CC;
    #pragma unroll
    for (int i = 0; i < 12; i++) {
        int c = lane + 32 * i;
        orow[c] = (v[i] - mu) * rstd * gw[c] + gb[c];
    }
}

// ---------------------------------------------------------------------------
// Generic TN SGEMM: C[m,n] = sum_k A[m,k] * W[n,k]  (+ fused epilogues)
//   A: MxK row-major, W: NxK row-major. Tile 128x128x16, 256 threads, 8x8/thr.
// MODE 0: out = acc + bias                                (qkv)
// MODE 1: out[map(m)] = acc + bias + res[map(m)]          (proj + rev + short)
// MODE 2: out = gelu(acc + bias)                          (mlp1)
// MODE 3: out = acc + bias + res[m]                       (mlp2 + residual)
// M % 128 == 0, N % 128 == 0, K % 16 == 0 (all true here).
// ---------------------------------------------------------------------------
template<int MODE>
__global__ __launch_bounds__(256, 2)
void sgemm_tn(const float* __restrict__ A, const float* __restrict__ Wt,
              const float* __restrict__ bias, float* __restrict__ Cout,
              int M, int N, int K, const float* __restrict__ res)
{
    __shared__ float As[16][132];
    __shared__ float Bs[16][132];

    const int tid = threadIdx.x;
    const int m0 = blockIdx.y * 128;
    const int n0 = blockIdx.x * 128;

    const int lrow = tid >> 2;          // 0..63
    const int lkc  = (tid & 3) << 2;    // 0,4,8,12
    const float* Ag = A  + (size_t)(m0 + lrow) * K + lkc;
    const float* Bg = Wt + (size_t)(n0 + lrow) * K + lkc;

    const int tm4 = (tid >> 4) << 2;    // 0..60 step 4
    const int tn4 = (tid & 15) << 2;    // 0..60 step 4

    float4 ra0, ra1, rb0, rb1;

#define FETCH(KT_) do {                                             \
        const float* Ag_ = Ag + (KT_) * 16;                         \
        const float* Bg_ = Bg + (KT_) * 16;                         \
        ra0 = *(const float4*)(Ag_);                                \
        ra1 = *(const float4*)(Ag_ + (size_t)64 * K);               \
        rb0 = *(const float4*)(Bg_);                                \
        rb1 = *(const float4*)(Bg_ + (size_t)64 * K);               \
    } while (0)

#define STORE() do {                                                            \
        As[lkc+0][lrow]    = ra0.x; As[lkc+1][lrow]    = ra0.y;                 \
        As[lkc+2][lrow]    = ra0.z; As[lkc+3][lrow]    = ra0.w;                 \
        As[lkc+0][lrow+64] = ra1.x; As[lkc+1][lrow+64] = ra1.y;                 \
        As[lkc+2][lrow+64] = ra1.z; As[lkc+3][lrow+64] = ra1.w;                 \
        Bs[lkc+0][lrow]    = rb0.x; Bs[lkc+1][lrow]    = rb0.y;                 \
        Bs[lkc+2][lrow]    = rb0.z; Bs[lkc+3][lrow]    = rb0.w;                 \
        Bs[lkc+0][lrow+64] = rb1.x; Bs[lkc+1][lrow+64] = rb1.y;                 \
        Bs[lkc+2][lrow+64] = rb1.z; Bs[lkc+3][lrow+64] = rb1.w;                 \
    } while (0)

    FETCH(0);
    STORE();
    __syncthreads();

    float acc[8][8];
    #pragma unroll
    for (int i = 0; i < 8; i++)
        #pragma unroll
        for (int j = 0; j < 8; j++) acc[i][j] = 0.f;

    const int KT = K >> 4;
    for (int kt = 0; kt < KT; kt++) {
        if (kt + 1 < KT) FETCH(kt + 1);

        #pragma unroll
        for (int k = 0; k < 16; k++) {
            float4 a0 = *(const float4*)(&As[k][tm4]);
            float4 a1 = *(const float4*)(&As[k][tm4 + 64]);
            float4 b0 = *(const float4*)(&Bs[k][tn4]);
            float4 b1 = *(const float4*)(&Bs[k][tn4 + 64]);
            float av[8] = {a0.x, a0.y, a0.z, a0.w, a1.x, a1.y, a1.z, a1.w};
            float bv[8] = {b0.x, b0.y, b0.z, b0.w, b1.x, b1.y, b1.z, b1.w};
            #pragma unroll
            for (int i = 0; i < 8; i++)
                #pragma unroll
                for (int j = 0; j < 8; j++)
                    acc[i][j] = fmaf(av[i], bv[j], acc[i][j]);
        }

        if (kt + 1 < KT) {
            __syncthreads();
            STORE();
            __syncthreads();
        }
    }
#undef FETCH
#undef STORE

    // epilogue
    #pragma unroll
    for (int ih = 0; ih < 2; ih++) {
        #pragma unroll
        for (int ii = 0; ii < 4; ii++) {
            int r    = m0 + ih * 64 + tm4 + ii;
            int ridx = ih * 4 + ii;
            int rdst = (MODE == 1) ? win_to_token(r) : r;
            #pragma unroll
            for (int jh = 0; jh < 2; jh++) {
                int c = n0 + jh * 64 + tn4;
                float4 bb = *(const float4*)(&bias[c]);
                float4 v;
                v.x = acc[ridx][jh*4+0] + bb.x;
                v.y = acc[ridx][jh*4+1] + bb.y;
                v.z = acc[ridx][jh*4+2] + bb.z;
                v.w = acc[ridx][jh*4+3] + bb.w;
                if (MODE == 1 || MODE == 3) {
                    float4 rr = *(const float4*)(&res[(size_t)rdst * N + c]);
                    v.x += rr.x; v.y += rr.y; v.z += rr.z; v.w += rr.w;
                }
                if (MODE == 2) {
                    v.x = gelu_exact(v.x); v.y = gelu_exact(v.y);
                    v.z = gelu_exact(v.z); v.w = gelu_exact(v.w);
                }
                *(float4*)(&Cout[(size_t)rdst * N + c]) = v;
            }
        }
    }
}

// ---------------------------------------------------------------------------
// Window attention: one block per (window, head). N=49, hd=32.
// Relative-position bias and shift mask computed on the fly.
// ---------------------------------------------------------------------------
__global__ __launch_bounds__(256)
void attn_kernel(const float* __restrict__ qkv,
                 const float* __restrict__ bias_table,
                 float* __restrict__ out)
{
    __shared__ float qs[49][36];
    __shared__ float ks[49][36];
    __shared__ float vs[49][36];
    __shared__ float S[49][52];
    __shared__ int   regid[49];

    const int w   = blockIdx.x;       // 0..1023
    const int h   = blockIdx.y;       // 0..11
    const int tid = threadIdx.x;
    const int wy  = (w >> 3) & 7;
    const int wx  = w & 7;

    if (tid < 49) {
        int iy = tid / 7, ix = tid - iy * 7;
        int hs = wy * 7 + iy;
        int ws = wx * 7 + ix;
        int rh = (hs < 49) ? 0 : ((hs < 53) ? 1 : 2);
        int rw = (ws < 49) ? 0 : ((ws < 53) ? 1 : 2);
        regid[tid] = rh * 3 + rw;
    }

    const float scale = 0.17677669529663687f;  // 1/sqrt(32)
    for (int idx = tid; idx < 49 * 8; idx += 256) {
        int p  = idx >> 3;
        int dc = (idx & 7) << 2;
        const float* base = qkv + (size_t)(w * 49 + p) * C3 + h * 32 + dc;
        float4 q4 = *(const float4*)(base);
        float4 k4 = *(const float4*)(base + 384);
        float4 v4 = *(const float4*)(base + 768);
        q4.x *= scale; q4.y *= scale; q4.z *= scale; q4.w *= scale;
        *(float4*)(&qs[p][dc]) = q4;
        *(float4*)(&ks[p][dc]) = k4;
        *(float4*)(&vs[p][dc]) = v4;
    }
    __syncthreads();

    // scores + relative bias + shift mask
    for (int idx = tid; idx < 49 * 49; idx += 256) {
        int i = idx / 49, j = idx - i * 49;
        float s = 0.f;
        #pragma unroll
        for (int d = 0; d < 32; d += 4) {
            float4 qa = *(const float4*)(&qs[i][d]);
            float4 kb = *(const float4*)(&ks[j][d]);
            s += qa.x * kb.x + qa.y * kb.y + qa.z * kb.z + qa.w * kb.w;
        }
        int iy = i / 7, ix = i - iy * 7;
        int jy = j / 7, jx = j - jy * 7;
        int rel = (iy - jy + 6) * 13 + (ix - jx + 6);
        s += bias_table[rel * NHEADS + h];
        if (regid[i] != regid[j]) s -= 100.0f;
        S[i][j] = s;
    }
    __syncthreads();

    // softmax, warp per row
    int warp = tid >> 5, lane = tid & 31;
    for (int i = warp; i < 49; i += 8) {
        float m = -1e30f;
        for (int j = lane; j < 49; j += 32) m = fmaxf(m, S[i][j]);
        #pragma unroll
        for (int o = 16; o; o >>= 1) m = fmaxf(m, __shfl_xor_sync(0xffffffffu, m, o));
        float sum = 0.f;
        for (int j = lane; j < 49; j += 32) {
            float e = __expf(S[i][j] - m);
            S[i][j] = e;
            sum += e;
        }
        #pragma unroll
        for (int o = 16; o; o >>= 1) sum += __shfl_xor_sync(0xffffffffu, sum, o);
        float inv = 1.0f / sum;
        for (int j = lane; j < 49; j += 32) S[i][j] *= inv;
    }
    __syncthreads();

    // O = P @ V, write head-interleaved (window-major rows, col = h*32+d)
    for (int idx = tid; idx < 49 * 32; idx += 256) {
        int i = idx >> 5, d = idx & 31;
        float acc = 0.f;
        #pragma unroll 7
        for (int j = 0; j < 49; j++) acc += S[i][j] * vs[j][d];
        out[(size_t)(w * 49 + i) * CC + h * 32 + d] = acc;
    }
}

// ---------------------------------------------------------------------------
// Host driver (graph-capturable: kernel launches only)
// ---------------------------------------------------------------------------
extern "C" void kernel_launch(void* const* d_in, const int* in_sizes, int n_in,
                              void* d_out, int out_size)
{
    const float* x      = (const float*)d_in[0];
    const float* n1w    = (const float*)d_in[1];
    const float* n1b    = (const float*)d_in[2];
    const float* qkv_w  = (const float*)d_in[3];
    const float* qkv_b  = (const float*)d_in[4];
    const float* btab   = (const float*)d_in[5];
    const float* proj_w = (const float*)d_in[6];
    const float* proj_b = (const float*)d_in[7];
    const float* n2w    = (const float*)d_in[8];
    const float* n2b    = (const float*)d_in[9];
    const float* w1     = (const float*)d_in[10];
    const float* b1     = (const float*)d_in[11];
    const float* w2     = (const float*)d_in[12];
    const float* b2     = (const float*)d_in[13];
    float* out = (float*)d_out;

    float *p_xw, *p_qkv, *p_attn, *p_xnew, *p_hid;
    cudaGetSymbolAddress((void**)&p_xw,   g_xw);
    cudaGetSymbolAddress((void**)&p_qkv,  g_qkv);
    cudaGetSymbolAddress((void**)&p_attn, g_attn);
    cudaGetSymbolAddress((void**)&p_xnew, g_xnew);
    cudaGetSymbolAddress((void**)&p_hid,  g_hid);

    const int MB = TOT / 128;   // 392

    // 1) LN1 + cyclic shift + window partition
    ln_kernel<true><<<TOT / 8, 256>>>(x, n1w, n1b, p_xw);

    // 2) QKV GEMM: (50176 x 384) @ (384 x 1152)
    sgemm_tn<0><<<dim3(C3 / 128, MB), 256>>>(p_xw, qkv_w, qkv_b, p_qkv,
                                             TOT, C3, CC, nullptr);

    // 3) window attention
    attn_kernel<<<dim3(NWIN, NHEADS), 256>>>(p_qkv, btab, p_attn);

    // 4) proj GEMM + window reverse + roll + shortcut add -> x_new
    sgemm_tn<1><<<dim3(CC / 128, MB), 256>>>(p_attn, proj_w, proj_b, p_xnew,
                                             TOT, CC, CC, x);

    // 5) LN2 (reuse g_xw)
    ln_kernel<false><<<TOT / 8, 256>>>(p_xnew, n2w, n2b, p_xw);

    // 6) MLP1 GEMM + exact GELU
    sgemm_tn<2><<<dim3(HIDDEN / 128, MB), 256>>>(p_xw, w1, b1, p_hid,
                                                 TOT, HIDDEN, CC, nullptr);

    // 7) MLP2 GEMM + residual -> d_out
    sgemm_tn<3><<<dim3(CC / 128, MB), 256>>>(p_hid, w2, b2, out,
                                             TOT, CC, HIDDEN, p_xnew);
}